// round 15
// baseline (speedup 1.0000x reference)
#include <cuda_runtime.h>
#include <cuda_fp16.h>
#include <cstdint>

// Problem constants
#define B_ 2
#define H_ 8
#define N_ 512
#define D_ 16
#define E_ 128
#define HD 128
#define THREADS 512

// smem layout (bytes). A/W rows are 128 fp16 = 256 B.
#define SM_Q     0                      // 512 B    q row, head-major
#define SM_S     512                    // 16384 B  scores [H][N]
#define SM_RED   16896                  // 64 B     softmax partials [H][2]
#define SM_OBUF  16960                  // 512 B    output partials [H][16]
#define SM_A     17920                  // 131072 B z fp16 [512m][128k] (FULL, resident)
#define SM_W     (SM_A + 131072)        // 65536 B  W fp16 [256n][128k] (d-permuted, interleaved)
#define SM_TOTAL (SM_W + 65536)         // 214528 B

// Precomputed W fp16 image (same byte layout as the SM_W smem region)
__device__ uint32_t g_Wbuf[256 * 64];   // 64 KB

__device__ __forceinline__ uint32_t smem_u32(const void* p) {
    uint32_t r;
    asm("{ .reg .u64 t; cvta.to.shared.u64 t, %1; cvt.u32.u64 %0, t; }" : "=r"(r) : "l"(p));
    return r;
}
__device__ __forceinline__ void cp16(uint32_t s, const void* g) {
    asm volatile("cp.async.cg.shared.global [%0], [%1], 16;" :: "r"(s), "l"(g));
}
#define CP_COMMIT() asm volatile("cp.async.commit_group;" ::: "memory")
#define CP_WAIT0()  asm volatile("cp.async.wait_group 0;" ::: "memory")
__device__ __forceinline__ void ldsm_x4(uint32_t (&r)[4], uint32_t addr) {
    asm volatile("ldmatrix.sync.aligned.m8n8.x4.shared.b16 {%0,%1,%2,%3}, [%4];"
                 : "=r"(r[0]), "=r"(r[1]), "=r"(r[2]), "=r"(r[3]) : "r"(addr));
}
#define MMA_F16(d, a, b0v, b1v) \
    asm volatile("mma.sync.aligned.m16n8k16.row.col.f32.f16.f16.f32 " \
        "{%0,%1,%2,%3}, {%4,%5,%6,%7}, {%8,%9}, {%0,%1,%2,%3};" \
        : "+f"((d)[0]), "+f"((d)[1]), "+f"((d)[2]), "+f"((d)[3]) \
        : "r"((a)[0]), "r"((a)[1]), "r"((a)[2]), "r"((a)[3]), "r"(b0v), "r"(b1v))

__device__ __forceinline__ uint32_t pack_hf2(__half a, __half b) {
    __half2 p = __halves2half2(a, b);
    return *reinterpret_cast<uint32_t*>(&p);
}

// =============== Prep kernel: W fp32 -> fp16 d-permuted swizzled image ===============
// Row nn encodes: h = nn>>5, ntl = (nn>>3)&3, tg = (nn>>1)&3, src = nn&1;
// source col c = h*16 + 4*tg + ntl of (src? Wz2 : Wz1).
__global__ void prep_w(const float* __restrict__ Wz1, const float* __restrict__ Wz2) {
    const int nn = blockIdx.x;          // 0..255
    const int e  = threadIdx.x * 2;     // 0..126 even
    const float* Wsrc = (nn & 1) ? Wz2 : Wz1;
    const int c = (nn >> 5) * 16 + ((nn >> 1) & 3) * 4 + ((nn >> 3) & 3);
    float w0 = Wsrc[e * HD + c];
    float w1 = Wsrc[(e + 1) * HD + c];
    uint32_t hi = pack_hf2(__float2half_rn(w0), __float2half_rn(w1));
    const int xr = nn & 7;
    int sw = ((((e >> 3) ^ xr) << 4)) + (e & 7) * 2;   // byte offset, multiple of 4
    g_Wbuf[nn * 64 + (sw >> 2)] = hi;
}

// =============== Main kernel: R13 structure, W via cp.async, 2 jobs per CTA ===============
__global__ void __launch_bounds__(THREADS, 1)
mixed_attn_free(const float* __restrict__ q, const float* __restrict__ k,
                const float* __restrict__ v, const float* __restrict__ z,
                float* __restrict__ out)
{
    extern __shared__ char smem[];
    const uint32_t smem_base = smem_u32(smem);
    float* q_sm   = (float*)(smem + SM_Q);
    float* s_sm   = (float*)(smem + SM_S);
    float* red_sm = (float*)(smem + SM_RED);
    float* obuf   = (float*)(smem + SM_OBUF);

    const int tid  = threadIdx.x;
    const int wid  = tid >> 5;
    const int lane = tid & 31;
    const int g    = lane >> 2;
    const int tig  = lane & 3;
    const int n = blockIdx.x;           // 0..511 ; jobs are (b=0,n), (b=1,n)

    // ---- W: coalesced async copy of the precomputed fp16 image (128 B per thread)
    {
        const uint32_t dst = smem_base + SM_W + tid * 128;
        const char* src = (const char*)g_Wbuf + tid * 128;
        #pragma unroll
        for (int i = 0; i < 8; i++) cp16(dst + i * 16, src + i * 16);
        CP_COMMIT();
    }

    // lane-invariant MMA addressing (16 warps = 4 m-groups x 4 n-groups)
    const int mgrp  = wid & 3;
    const int ngrp  = wid >> 2;
    const int laneX = lane & 7;
    const uint32_t arow = smem_base + SM_A +
        (uint32_t)(mgrp * 32 + ((lane >> 3) & 1) * 8 + laneX) * 256;
    const int asel = lane >> 4;
    const uint32_t brow = smem_base + SM_W +
        (uint32_t)(ngrp * 64 + ((lane >> 4) & 1) * 8 + laneX) * 256;
    const int bsel = (lane >> 3) & 1;
    const int h0 = ngrp * 2;

    #pragma unroll 1
    for (int b = 0; b < B_; b++) {
        // ================= PHASE 1: z -> fp16 A (1 row/thread), q =================
        {
            const float4* zr = (const float4*)(z + (((size_t)b * N_ + n) * N_ + tid) * E_);
            char* AH = smem + SM_A + tid * 256;
            const int xr = tid & 7;
            #pragma unroll 1
            for (int j0 = 0; j0 < 32; j0 += 8) {
                float4 f[8];
                #pragma unroll
                for (int j = 0; j < 8; j++) f[j] = zr[j0 + j];
                #pragma unroll
                for (int j = 0; j < 8; j++) {
                    const int e = (j0 + j) * 4;
                    uint32_t h01 = pack_hf2(__float2half_rn(f[j].x), __float2half_rn(f[j].y));
                    uint32_t h23 = pack_hf2(__float2half_rn(f[j].z), __float2half_rn(f[j].w));
                    int sw = (((e >> 3) ^ xr) << 4) + (e & 4) * 2;
                    *(uint2*)(AH + sw) = make_uint2(h01, h23);
                }
            }
        }
        if (tid < HD) {
            int h = tid >> 4, d = tid & 15;
            q_sm[tid] = q[(((size_t)b * H_ + h) * N_ + n) * D_ + d];
        }
        if (b == 0) CP_WAIT0();     // W image resident
        __syncthreads();            // A, W, q ready

        // ================= PHASE 2: barrier-free MMA + scores =================
        {
            const float* kh0 = k + (((size_t)b * H_ + h0) * N_) * D_;
            const float* kh1 = k + (((size_t)b * H_ + h0 + 1) * N_) * D_;
            const float4 q40 = ((const float4*)(q_sm + h0 * 16))[tig];
            const float4 q41 = ((const float4*)(q_sm + (h0 + 1) * 16))[tig];

            #pragma unroll 1
            for (int chunk = 0; chunk < 4; chunk++) {
                const uint32_t abase = arow + (uint32_t)chunk * (128 * 256);

                float acc[2][8][4];
                #pragma unroll
                for (int mt = 0; mt < 2; mt++)
                    #pragma unroll
                    for (int nt = 0; nt < 8; nt++)
                        #pragma unroll
                        for (int i = 0; i < 4; i++) acc[mt][nt][i] = 0.f;

                #pragma unroll 2
                for (int ks = 0; ks < 8; ks++) {
                    uint32_t ah[2][4];
                    const uint32_t aoff = abase + ((uint32_t)((ks * 2 + asel) ^ laneX) << 4);
                    ldsm_x4(ah[0], aoff);
                    ldsm_x4(ah[1], aoff + 16 * 256);
                    const uint32_t boff = ((uint32_t)((ks * 2 + bsel) ^ laneX) << 4);
                    #pragma unroll
                    for (int ntp = 0; ntp < 4; ntp++) {
                        uint32_t bh[4];
                        ldsm_x4(bh, brow + (uint32_t)ntp * (16 * 256) + boff);
                        #pragma unroll
                        for (int mt = 0; mt < 2; mt++) {
                            MMA_F16(acc[mt][2 * ntp],     ah[mt], bh[0], bh[1]);
                            MMA_F16(acc[mt][2 * ntp + 1], ah[mt], bh[2], bh[3]);
                        }
                    }
                }

                // scores: fragment (ntl,tig) holds d = 4*tig+ntl -> one float4 k load per row
                #pragma unroll
                for (int hh = 0; hh < 2; hh++) {
                    const int h = h0 + hh;
                    const float* kh = hh ? kh1 : kh0;
                    const float4 q4 = hh ? q41 : q40;
                    #pragma unroll
                    for (int mt = 0; mt < 2; mt++) {
                        #pragma unroll
                        for (int r = 0; r < 2; r++) {
                            const int mg = chunk * 128 + mgrp * 32 + mt * 16 + r * 8 + g;
                            const float4 kv = *(const float4*)(kh + (size_t)mg * 16 + 4 * tig);
                            float s;
                            s  = (q4.x + acc[mt][hh * 4 + 0][2 * r]) * (kv.x + acc[mt][hh * 4 + 0][2 * r + 1]);
                            s += (q4.y + acc[mt][hh * 4 + 1][2 * r]) * (kv.y + acc[mt][hh * 4 + 1][2 * r + 1]);
                            s += (q4.z + acc[mt][hh * 4 + 2][2 * r]) * (kv.z + acc[mt][hh * 4 + 2][2 * r + 1]);
                            s += (q4.w + acc[mt][hh * 4 + 3][2 * r]) * (kv.w + acc[mt][hh * 4 + 3][2 * r + 1]);
                            s += __shfl_xor_sync(0xffffffffu, s, 1);
                            s += __shfl_xor_sync(0xffffffffu, s, 2);
                            if (tig == 0)
                                s_sm[h * N_ + mg] = s * 0.25f;   // 1/sqrt(D), D=16
                        }
                    }
                }
            }
        }
        __syncthreads();   // all scores written

        // ================= PHASE 3: softmax + output =================
        {
            const int h    = wid & 7;
            const int half = wid >> 3;
            float* srow = s_sm + h * N_;

            float mx = -1e30f;
            for (int m = lane; m < N_; m += 32) mx = fmaxf(mx, srow[m]);
            #pragma unroll
            for (int o = 16; o > 0; o >>= 1) mx = fmaxf(mx, __shfl_xor_sync(0xffffffffu, mx, o));

            float psum = 0.f;
            const int mbeg = half * (N_ / 2);
            for (int m = mbeg + lane; m < mbeg + N_ / 2; m += 32) {
                float e = __expf(srow[m] - mx);
                srow[m] = e;
                psum += e;
            }
            #pragma unroll
            for (int o = 16; o > 0; o >>= 1) psum += __shfl_xor_sync(0xffffffffu, psum, o);
            if (lane == 0) red_sm[h * 2 + half] = psum;
            __syncthreads();
            const float sum = red_sm[h * 2] + red_sm[h * 2 + 1];

            const int d   = lane & 15;
            const int sub = lane >> 4;
            const float* vp = v + (((size_t)b * H_ + h) * N_) * D_;
            float oacc = 0.f;
            const int m0 = mbeg + sub * (N_ / 4);
            #pragma unroll 4
            for (int m = m0; m < m0 + N_ / 4; m++)
                oacc += srow[m] * vp[(size_t)m * D_ + d];
            oacc += __shfl_xor_sync(0xffffffffu, oacc, 16);
            if (half == 1 && sub == 0) obuf[h * 16 + d] = oacc;
            __syncthreads();
            if (half == 0 && sub == 0)
                out[((size_t)b * N_ + n) * HD + h * 16 + d] = (oacc + obuf[h * 16 + d]) / sum;
        }
        __syncthreads();   // scores/A reusable for next job
    }
}

extern "C" void kernel_launch(void* const* d_in, const int* in_sizes, int n_in,
                              void* d_out, int out_size) {
    const float* q   = (const float*)d_in[0];
    const float* k   = (const float*)d_in[1];
    const float* v   = (const float*)d_in[2];
    const float* z   = (const float*)d_in[3];
    const float* Wz1 = (const float*)d_in[4];
    const float* Wz2 = (const float*)d_in[5];
    float* out = (float*)d_out;

    prep_w<<<256, 64>>>(Wz1, Wz2);

    cudaFuncSetAttribute(mixed_attn_free,
                         cudaFuncAttributeMaxDynamicSharedMemorySize, SM_TOTAL);
    mixed_attn_free<<<N_, THREADS, SM_TOTAL>>>(q, k, v, z, out);
}

// round 16
// speedup vs baseline: 1.1054x; 1.1054x over previous
#include <cuda_runtime.h>
#include <cuda_fp16.h>
#include <cstdint>

// Problem constants
#define B_ 2
#define H_ 8
#define N_ 512
#define D_ 16
#define E_ 128
#define HD 128
#define THREADS 512

// smem layout (bytes). A/W rows are 128 fp16 = 256 B.
#define SM_Q     0                      // 512 B    q row, head-major
#define SM_S     512                    // 16384 B  scores [H][N]
#define SM_RED   16896                  // 64 B     softmax partials [H][2]
#define SM_OBUF  16960                  // 512 B    output partials [H][16]
#define SM_A     17920                  // 131072 B z fp16 [512m][128k] (FULL, resident)
#define SM_W     (SM_A + 131072)        // 65536 B  W fp16 [256n][128k] (d-permuted, interleaved)
#define SM_TOTAL (SM_W + 65536)         // 214528 B

// Precomputed W fp16 image (same byte layout as the SM_W smem region)
__device__ uint32_t g_Wbuf[256 * 64];   // 64 KB

__device__ __forceinline__ uint32_t smem_u32(const void* p) {
    uint32_t r;
    asm("{ .reg .u64 t; cvta.to.shared.u64 t, %1; cvt.u32.u64 %0, t; }" : "=r"(r) : "l"(p));
    return r;
}
__device__ __forceinline__ void cp16(uint32_t s, const void* g) {
    asm volatile("cp.async.cg.shared.global [%0], [%1], 16;" :: "r"(s), "l"(g));
}
#define CP_COMMIT() asm volatile("cp.async.commit_group;" ::: "memory")
#define CP_WAIT0()  asm volatile("cp.async.wait_group 0;" ::: "memory")
__device__ __forceinline__ void ldsm_x4(uint32_t (&r)[4], uint32_t addr) {
    asm volatile("ldmatrix.sync.aligned.m8n8.x4.shared.b16 {%0,%1,%2,%3}, [%4];"
                 : "=r"(r[0]), "=r"(r[1]), "=r"(r[2]), "=r"(r[3]) : "r"(addr));
}
#define MMA_F16(d, a, b0v, b1v) \
    asm volatile("mma.sync.aligned.m16n8k16.row.col.f32.f16.f16.f32 " \
        "{%0,%1,%2,%3}, {%4,%5,%6,%7}, {%8,%9}, {%0,%1,%2,%3};" \
        : "+f"((d)[0]), "+f"((d)[1]), "+f"((d)[2]), "+f"((d)[3]) \
        : "r"((a)[0]), "r"((a)[1]), "r"((a)[2]), "r"((a)[3]), "r"(b0v), "r"(b1v))

__device__ __forceinline__ uint32_t pack_hf2(__half a, __half b) {
    __half2 p = __halves2half2(a, b);
    return *reinterpret_cast<uint32_t*>(&p);
}

// =============== Prep kernel: W fp32 -> fp16 d-permuted swizzled image ===============
// Row nn encodes: h = nn>>5, ntl = (nn>>3)&3, tg = (nn>>1)&3, src = nn&1;
// source col c = h*16 + 4*tg + ntl of (src? Wz2 : Wz1).
__global__ void prep_w(const float* __restrict__ Wz1, const float* __restrict__ Wz2) {
    const int nn = blockIdx.x;          // 0..255
    const int e  = threadIdx.x * 2;     // 0..126 even
    const float* Wsrc = (nn & 1) ? Wz2 : Wz1;
    const int c = (nn >> 5) * 16 + ((nn >> 1) & 3) * 4 + ((nn >> 3) & 3);
    float w0 = Wsrc[e * HD + c];
    float w1 = Wsrc[(e + 1) * HD + c];
    uint32_t hi = pack_hf2(__float2half_rn(w0), __float2half_rn(w1));
    const int xr = nn & 7;
    int sw = ((((e >> 3) ^ xr) << 4)) + (e & 7) * 2;   // byte offset, multiple of 4
    g_Wbuf[nn * 64 + (sw >> 2)] = hi;
}

// =============== Main kernel: R13 structure, W via cp.async, grid = 1024 ===============
__global__ void __launch_bounds__(THREADS, 1)
mixed_attn_free(const float* __restrict__ q, const float* __restrict__ k,
                const float* __restrict__ v, const float* __restrict__ z,
                float* __restrict__ out)
{
    extern __shared__ char smem[];
    const uint32_t smem_base = smem_u32(smem);
    float* q_sm   = (float*)(smem + SM_Q);
    float* s_sm   = (float*)(smem + SM_S);
    float* red_sm = (float*)(smem + SM_RED);
    float* obuf   = (float*)(smem + SM_OBUF);

    const int tid  = threadIdx.x;
    const int wid  = tid >> 5;
    const int lane = tid & 31;
    const int g    = lane >> 2;
    const int tig  = lane & 3;
    const int n = blockIdx.x, b = blockIdx.y;

    // ---- W: coalesced async copy of the precomputed fp16 image (128 B per thread),
    // issued first so it arrives under the z-convert phase.
    {
        const uint32_t dst = smem_base + SM_W + tid * 128;
        const char* src = (const char*)g_Wbuf + tid * 128;
        #pragma unroll
        for (int i = 0; i < 8; i++) cp16(dst + i * 16, src + i * 16);
        CP_COMMIT();
    }

    // =========================== PHASE 1: cooperative convert ===========================
    // z: one full m-row per thread (128 floats, contiguous 512 B) -> fp16 A row
    {
        const float4* zr = (const float4*)(z + (((size_t)b * N_ + n) * N_ + tid) * E_);
        char* AH = smem + SM_A + tid * 256;
        const int xr = tid & 7;
        #pragma unroll 1
        for (int j0 = 0; j0 < 32; j0 += 8) {
            float4 f[8];
            #pragma unroll
            for (int j = 0; j < 8; j++) f[j] = zr[j0 + j];
            #pragma unroll
            for (int j = 0; j < 8; j++) {
                const int e = (j0 + j) * 4;
                uint32_t h01 = pack_hf2(__float2half_rn(f[j].x), __float2half_rn(f[j].y));
                uint32_t h23 = pack_hf2(__float2half_rn(f[j].z), __float2half_rn(f[j].w));
                int sw = (((e >> 3) ^ xr) << 4) + (e & 4) * 2;
                *(uint2*)(AH + sw) = make_uint2(h01, h23);
            }
        }
    }
    // q row, head-major
    if (tid < HD) {
        int h = tid >> 4, d = tid & 15;
        q_sm[tid] = q[(((size_t)b * H_ + h) * N_ + n) * D_ + d];
    }
    CP_WAIT0();        // W image resident
    __syncthreads();   // A, W, q all resident

    // =========================== PHASE 2: barrier-free MMA + scores ===========================
    // 16 warps = 4 m-groups x 4 n-groups; each warp: 4 chunks of 32m x 64n (2 heads), K=128.
    {
        const int mgrp  = wid & 3;
        const int ngrp  = wid >> 2;
        const int nbase = ngrp * 64;
        const int laneX = lane & 7;
        const uint32_t arow = smem_base + SM_A +
            (uint32_t)(mgrp * 32 + ((lane >> 3) & 1) * 8 + laneX) * 256;
        const int asel = lane >> 4;
        const uint32_t brow = smem_base + SM_W +
            (uint32_t)(nbase + ((lane >> 4) & 1) * 8 + laneX) * 256;
        const int bsel = (lane >> 3) & 1;

        const int h0 = ngrp * 2;
        const float* kh0 = k + (((size_t)b * H_ + h0) * N_) * D_;
        const float* kh1 = k + (((size_t)b * H_ + h0 + 1) * N_) * D_;
        const float4 q40 = ((const float4*)(q_sm + h0 * 16))[tig];
        const float4 q41 = ((const float4*)(q_sm + (h0 + 1) * 16))[tig];

        #pragma unroll 1
        for (int chunk = 0; chunk < 4; chunk++) {
            const uint32_t abase = arow + (uint32_t)chunk * (128 * 256);

            float acc[2][8][4];
            #pragma unroll
            for (int mt = 0; mt < 2; mt++)
                #pragma unroll
                for (int nt = 0; nt < 8; nt++)
                    #pragma unroll
                    for (int i = 0; i < 4; i++) acc[mt][nt][i] = 0.f;

            #pragma unroll 2
            for (int ks = 0; ks < 8; ks++) {
                uint32_t ah[2][4];
                const uint32_t aoff = abase + ((uint32_t)((ks * 2 + asel) ^ laneX) << 4);
                ldsm_x4(ah[0], aoff);
                ldsm_x4(ah[1], aoff + 16 * 256);
                const uint32_t boff = ((uint32_t)((ks * 2 + bsel) ^ laneX) << 4);
                #pragma unroll
                for (int ntp = 0; ntp < 4; ntp++) {
                    uint32_t bh[4];
                    ldsm_x4(bh, brow + (uint32_t)ntp * (16 * 256) + boff);
                    #pragma unroll
                    for (int mt = 0; mt < 2; mt++) {
                        MMA_F16(acc[mt][2 * ntp],     ah[mt], bh[0], bh[1]);
                        MMA_F16(acc[mt][2 * ntp + 1], ah[mt], bh[2], bh[3]);
                    }
                }
            }

            // scores: fragment (ntl,tig) holds d = 4*tig+ntl -> one float4 k load per row
            #pragma unroll
            for (int hh = 0; hh < 2; hh++) {
                const int h = h0 + hh;
                const float* kh = hh ? kh1 : kh0;
                const float4 q4 = hh ? q41 : q40;
                #pragma unroll
                for (int mt = 0; mt < 2; mt++) {
                    #pragma unroll
                    for (int r = 0; r < 2; r++) {
                        const int mg = chunk * 128 + mgrp * 32 + mt * 16 + r * 8 + g;
                        const float4 kv = *(const float4*)(kh + (size_t)mg * 16 + 4 * tig);
                        float s;
                        s  = (q4.x + acc[mt][hh * 4 + 0][2 * r]) * (kv.x + acc[mt][hh * 4 + 0][2 * r + 1]);
                        s += (q4.y + acc[mt][hh * 4 + 1][2 * r]) * (kv.y + acc[mt][hh * 4 + 1][2 * r + 1]);
                        s += (q4.z + acc[mt][hh * 4 + 2][2 * r]) * (kv.z + acc[mt][hh * 4 + 2][2 * r + 1]);
                        s += (q4.w + acc[mt][hh * 4 + 3][2 * r]) * (kv.w + acc[mt][hh * 4 + 3][2 * r + 1]);
                        s += __shfl_xor_sync(0xffffffffu, s, 1);
                        s += __shfl_xor_sync(0xffffffffu, s, 2);
                        if (tig == 0)
                            s_sm[h * N_ + mg] = s * 0.25f;   // 1/sqrt(D), D=16
                    }
                }
            }
        }
    }
    __syncthreads();   // all scores written

    // =========================== PHASE 3: softmax + output ===========================
    {
        const int h    = wid & 7;
        const int half = wid >> 3;
        float* srow = s_sm + h * N_;

        float mx = -1e30f;
        for (int m = lane; m < N_; m += 32) mx = fmaxf(mx, srow[m]);
        #pragma unroll
        for (int o = 16; o > 0; o >>= 1) mx = fmaxf(mx, __shfl_xor_sync(0xffffffffu, mx, o));

        float psum = 0.f;
        const int mbeg = half * (N_ / 2);
        for (int m = mbeg + lane; m < mbeg + N_ / 2; m += 32) {
            float e = __expf(srow[m] - mx);
            srow[m] = e;
            psum += e;
        }
        #pragma unroll
        for (int o = 16; o > 0; o >>= 1) psum += __shfl_xor_sync(0xffffffffu, psum, o);
        if (lane == 0) red_sm[h * 2 + half] = psum;
        __syncthreads();
        const float sum = red_sm[h * 2] + red_sm[h * 2 + 1];

        const int d   = lane & 15;
        const int sub = lane >> 4;
        const float* vp = v + (((size_t)b * H_ + h) * N_) * D_;
        float oacc = 0.f;
        const int m0 = mbeg + sub * (N_ / 4);
        #pragma unroll 4
        for (int m = m0; m < m0 + N_ / 4; m++)
            oacc += srow[m] * vp[(size_t)m * D_ + d];
        oacc += __shfl_xor_sync(0xffffffffu, oacc, 16);
        if (half == 1 && sub == 0) obuf[h * 16 + d] = oacc;
        __syncthreads();
        if (half == 0 && sub == 0)
            out[((size_t)b * N_ + n) * HD + h * 16 + d] = (oacc + obuf[h * 16 + d]) / sum;
    }
}

extern "C" void kernel_launch(void* const* d_in, const int* in_sizes, int n_in,
                              void* d_out, int out_size) {
    const float* q   = (const float*)d_in[0];
    const float* k   = (const float*)d_in[1];
    const float* v   = (const float*)d_in[2];
    const float* z   = (const float*)d_in[3];
    const float* Wz1 = (const float*)d_in[4];
    const float* Wz2 = (const float*)d_in[5];
    float* out = (float*)d_out;

    prep_w<<<256, 64>>>(Wz1, Wz2);

    cudaFuncSetAttribute(mixed_attn_free,
                         cudaFuncAttributeMaxDynamicSharedMemorySize, SM_TOTAL);
    dim3 grid(N_, B_);
    mixed_attn_free<<<grid, THREADS, SM_TOTAL>>>(q, k, v, z, out);
}

// round 17
// speedup vs baseline: 1.3096x; 1.1847x over previous
#include <cuda_runtime.h>
#include <cuda_fp16.h>
#include <cstdint>

// Problem constants
#define B_ 2
#define H_ 8
#define N_ 512
#define D_ 16
#define E_ 128
#define HD 128
#define THREADS 512

// smem layout (bytes). A/W rows are 128 fp16 = 256 B.
#define SM_Q     0                      // 512 B    q row, head-major
#define SM_S     512                    // 16384 B  scores [H][N]
#define SM_RED   16896                  // 64 B     softmax partials [H][2]
#define SM_OBUF  16960                  // 512 B    output partials [H][16]
#define SM_A     17920                  // 131072 B z fp16 [512m][128k] (FULL, resident)
#define SM_W     (SM_A + 131072)        // 65536 B  W fp16 [256n][128k] (d-permuted, interleaved)
#define SM_TOTAL (SM_W + 65536)         // 214528 B

// Precomputed W fp16 image (same byte layout as the SM_W smem region)
__device__ uint32_t g_Wbuf[256 * 64];   // 64 KB

__device__ __forceinline__ uint32_t smem_u32(const void* p) {
    uint32_t r;
    asm("{ .reg .u64 t; cvta.to.shared.u64 t, %1; cvt.u32.u64 %0, t; }" : "=r"(r) : "l"(p));
    return r;
}
__device__ __forceinline__ void cp16(uint32_t s, const void* g) {
    asm volatile("cp.async.cg.shared.global [%0], [%1], 16;" :: "r"(s), "l"(g));
}
#define CP_COMMIT() asm volatile("cp.async.commit_group;" ::: "memory")
#define CP_WAIT0()  asm volatile("cp.async.wait_group 0;" ::: "memory")
__device__ __forceinline__ void ldsm_x4(uint32_t (&r)[4], uint32_t addr) {
    asm volatile("ldmatrix.sync.aligned.m8n8.x4.shared.b16 {%0,%1,%2,%3}, [%4];"
                 : "=r"(r[0]), "=r"(r[1]), "=r"(r[2]), "=r"(r[3]) : "r"(addr));
}
#define MMA_F16(d, a, b0v, b1v) \
    asm volatile("mma.sync.aligned.m16n8k16.row.col.f32.f16.f16.f32 " \
        "{%0,%1,%2,%3}, {%4,%5,%6,%7}, {%8,%9}, {%0,%1,%2,%3};" \
        : "+f"((d)[0]), "+f"((d)[1]), "+f"((d)[2]), "+f"((d)[3]) \
        : "r"((a)[0]), "r"((a)[1]), "r"((a)[2]), "r"((a)[3]), "r"(b0v), "r"(b1v))

__device__ __forceinline__ uint32_t pack_hf2(__half a, __half b) {
    __half2 p = __halves2half2(a, b);
    return *reinterpret_cast<uint32_t*>(&p);
}

// =============== Prep kernel: W fp32 -> fp16 d-permuted swizzled image ===============
// Row nn encodes: h = nn>>5, ntl = (nn>>3)&3, tg = (nn>>1)&3, src = nn&1;
// source col c = h*16 + 4*tg + ntl of (src? Wz2 : Wz1).
__global__ void prep_w(const float* __restrict__ Wz1, const float* __restrict__ Wz2) {
    const int nn = blockIdx.x;          // 0..255
    const int e  = threadIdx.x * 2;     // 0..126 even
    const float* Wsrc = (nn & 1) ? Wz2 : Wz1;
    const int c = (nn >> 5) * 16 + ((nn >> 1) & 3) * 4 + ((nn >> 3) & 3);
    float w0 = Wsrc[e * HD + c];
    float w1 = Wsrc[(e + 1) * HD + c];
    uint32_t hi = pack_hf2(__float2half_rn(w0), __float2half_rn(w1));
    const int xr = nn & 7;
    int sw = ((((e >> 3) ^ xr) << 4)) + (e & 7) * 2;   // byte offset, multiple of 4
    g_Wbuf[nn * 64 + (sw >> 2)] = hi;
}

// =============== Main kernel: R16 structure + coalesced phase-1 z loading ===============
__global__ void __launch_bounds__(THREADS, 1)
mixed_attn_free(const float* __restrict__ q, const float* __restrict__ k,
                const float* __restrict__ v, const float* __restrict__ z,
                float* __restrict__ out)
{
    extern __shared__ char smem[];
    const uint32_t smem_base = smem_u32(smem);
    float* q_sm   = (float*)(smem + SM_Q);
    float* s_sm   = (float*)(smem + SM_S);
    float* red_sm = (float*)(smem + SM_RED);
    float* obuf   = (float*)(smem + SM_OBUF);

    const int tid  = threadIdx.x;
    const int wid  = tid >> 5;
    const int lane = tid & 31;
    const int g    = lane >> 2;
    const int tig  = lane & 3;
    const int n = blockIdx.x, b = blockIdx.y;

    // ---- W: coalesced async copy of the precomputed fp16 image (128 B per thread),
    // issued first so it arrives under the z-convert phase.
    {
        const uint32_t dst = smem_base + SM_W + tid * 128;
        const char* src = (const char*)g_Wbuf + tid * 128;
        #pragma unroll
        for (int i = 0; i < 8; i++) cp16(dst + i * 16, src + i * 16);
        CP_COMMIT();
    }

    // =========================== PHASE 1: cooperative convert (COALESCED) ===========================
    // Warp w sweeps rows w*32 .. w*32+31. Lane l loads float4 z[row][4l]
    // (one warp instruction = one contiguous 512-B row = 4 lines), converts its
    // 4 floats, stores 8 B to the swizzled slot for e = 4l. Conversion is
    // elementwise so no thread needs the whole row.
    {
        const float* zjob = z + (((size_t)b * N_ + n) * N_) * E_;
        const int e = lane * 4;                       // this lane's 4 e-values
        const int eoff = ((e >> 3) << 4) + (e & 4) * 2;  // pre-swizzle (xr applied per row)
        #pragma unroll 8
        for (int rr = 0; rr < 32; rr++) {
            const int row = wid * 32 + rr;
            float4 f = ((const float4*)(zjob + (size_t)row * E_))[lane];
            uint32_t h01 = pack_hf2(__float2half_rn(f.x), __float2half_rn(f.y));
            uint32_t h23 = pack_hf2(__float2half_rn(f.z), __float2half_rn(f.w));
            int sw = eoff ^ ((row & 7) << 4);
            *(uint2*)(smem + SM_A + row * 256 + sw) = make_uint2(h01, h23);
        }
    }
    // q row, head-major
    if (tid < HD) {
        int h = tid >> 4, d = tid & 15;
        q_sm[tid] = q[(((size_t)b * H_ + h) * N_ + n) * D_ + d];
    }
    CP_WAIT0();        // W image resident
    __syncthreads();   // A, W, q all resident

    // =========================== PHASE 2: barrier-free MMA + scores ===========================
    // 16 warps = 4 m-groups x 4 n-groups; each warp: 4 chunks of 32m x 64n (2 heads), K=128.
    {
        const int mgrp  = wid & 3;
        const int ngrp  = wid >> 2;
        const int nbase = ngrp * 64;
        const int laneX = lane & 7;
        const uint32_t arow = smem_base + SM_A +
            (uint32_t)(mgrp * 32 + ((lane >> 3) & 1) * 8 + laneX) * 256;
        const int asel = lane >> 4;
        const uint32_t brow = smem_base + SM_W +
            (uint32_t)(nbase + ((lane >> 4) & 1) * 8 + laneX) * 256;
        const int bsel = (lane >> 3) & 1;

        const int h0 = ngrp * 2;
        const float* kh0 = k + (((size_t)b * H_ + h0) * N_) * D_;
        const float* kh1 = k + (((size_t)b * H_ + h0 + 1) * N_) * D_;
        const float4 q40 = ((const float4*)(q_sm + h0 * 16))[tig];
        const float4 q41 = ((const float4*)(q_sm + (h0 + 1) * 16))[tig];

        #pragma unroll 1
        for (int chunk = 0; chunk < 4; chunk++) {
            const uint32_t abase = arow + (uint32_t)chunk * (128 * 256);

            float acc[2][8][4];
            #pragma unroll
            for (int mt = 0; mt < 2; mt++)
                #pragma unroll
                for (int nt = 0; nt < 8; nt++)
                    #pragma unroll
                    for (int i = 0; i < 4; i++) acc[mt][nt][i] = 0.f;

            #pragma unroll 2
            for (int ks = 0; ks < 8; ks++) {
                uint32_t ah[2][4];
                const uint32_t aoff = abase + ((uint32_t)((ks * 2 + asel) ^ laneX) << 4);
                ldsm_x4(ah[0], aoff);
                ldsm_x4(ah[1], aoff + 16 * 256);
                const uint32_t boff = ((uint32_t)((ks * 2 + bsel) ^ laneX) << 4);
                #pragma unroll
                for (int ntp = 0; ntp < 4; ntp++) {
                    uint32_t bh[4];
                    ldsm_x4(bh, brow + (uint32_t)ntp * (16 * 256) + boff);
                    #pragma unroll
                    for (int mt = 0; mt < 2; mt++) {
                        MMA_F16(acc[mt][2 * ntp],     ah[mt], bh[0], bh[1]);
                        MMA_F16(acc[mt][2 * ntp + 1], ah[mt], bh[2], bh[3]);
                    }
                }
            }

            // scores: fragment (ntl,tig) holds d = 4*tig+ntl -> one float4 k load per row
            #pragma unroll
            for (int hh = 0; hh < 2; hh++) {
                const int h = h0 + hh;
                const float* kh = hh ? kh1 : kh0;
                const float4 q4 = hh ? q41 : q40;
                #pragma unroll
                for (int mt = 0; mt < 2; mt++) {
                    #pragma unroll
                    for (int r = 0; r < 2; r++) {
                        const int mg = chunk * 128 + mgrp * 32 + mt * 16 + r * 8 + g;
                        const float4 kv = *(const float4*)(kh + (size_t)mg * 16 + 4 * tig);
                        float s;
                        s  = (q4.x + acc[mt][hh * 4 + 0][2 * r]) * (kv.x + acc[mt][hh * 4 + 0][2 * r + 1]);
                        s += (q4.y + acc[mt][hh * 4 + 1][2 * r]) * (kv.y + acc[mt][hh * 4 + 1][2 * r + 1]);
                        s += (q4.z + acc[mt][hh * 4 + 2][2 * r]) * (kv.z + acc[mt][hh * 4 + 2][2 * r + 1]);
                        s += (q4.w + acc[mt][hh * 4 + 3][2 * r]) * (kv.w + acc[mt][hh * 4 + 3][2 * r + 1]);
                        s += __shfl_xor_sync(0xffffffffu, s, 1);
                        s += __shfl_xor_sync(0xffffffffu, s, 2);
                        if (tig == 0)
                            s_sm[h * N_ + mg] = s * 0.25f;   // 1/sqrt(D), D=16
                    }
                }
            }
        }
    }
    __syncthreads();   // all scores written

    // =========================== PHASE 3: softmax + output ===========================
    {
        const int h    = wid & 7;
        const int half = wid >> 3;
        float* srow = s_sm + h * N_;

        float mx = -1e30f;
        for (int m = lane; m < N_; m += 32) mx = fmaxf(mx, srow[m]);
        #pragma unroll
        for (int o = 16; o > 0; o >>= 1) mx = fmaxf(mx, __shfl_xor_sync(0xffffffffu, mx, o));

        float psum = 0.f;
        const int mbeg = half * (N_ / 2);
        for (int m = mbeg + lane; m < mbeg + N_ / 2; m += 32) {
            float e = __expf(srow[m] - mx);
            srow[m] = e;
            psum += e;
        }
        #pragma unroll
        for (int o = 16; o > 0; o >>= 1) psum += __shfl_xor_sync(0xffffffffu, psum, o);
        if (lane == 0) red_sm[h * 2 + half] = psum;
        __syncthreads();
        const float sum = red_sm[h * 2] + red_sm[h * 2 + 1];

        const int d   = lane & 15;
        const int sub = lane >> 4;
        const float* vp = v + (((size_t)b * H_ + h) * N_) * D_;
        float oacc = 0.f;
        const int m0 = mbeg + sub * (N_ / 4);
        #pragma unroll 4
        for (int m = m0; m < m0 + N_ / 4; m++)
            oacc += srow[m] * vp[(size_t)m * D_ + d];
        oacc += __shfl_xor_sync(0xffffffffu, oacc, 16);
        if (half == 1 && sub == 0) obuf[h * 16 + d] = oacc;
        __syncthreads();
        if (half == 0 && sub == 0)
            out[((size_t)b * N_ + n) * HD + h * 16 + d] = (oacc + obuf[h * 16 + d]) / sum;
    }
}

extern "C" void kernel_launch(void* const* d_in, const int* in_sizes, int n_in,
                              void* d_out, int out_size) {
    const float* q   = (const float*)d_in[0];
    const float* k   = (const float*)d_in[1];
    const float* v   = (const float*)d_in[2];
    const float* z   = (const float*)d_in[3];
    const float* Wz1 = (const float*)d_in[4];
    const float* Wz2 = (const float*)d_in[5];
    float* out = (float*)d_out;

    prep_w<<<256, 64>>>(Wz1, Wz2);

    cudaFuncSetAttribute(mixed_attn_free,
                         cudaFuncAttributeMaxDynamicSharedMemorySize, SM_TOTAL);
    dim3 grid(N_, B_);
    mixed_attn_free<<<grid, THREADS, SM_TOTAL>>>(q, k, v, z, out);
}